// round 6
// baseline (speedup 1.0000x reference)
#include <cuda_runtime.h>
#include <cuda_bf16.h>
#include <cstdint>

#define HDIM 20
#define TPB 32   // one warp per block; lane parity = role; 2 elements per thread

typedef unsigned long long u64;

union F2u { float2 f; u64 u; };
union F4u { float4 f; u64 u[2]; };

__device__ __forceinline__ u64 pack2(float lo, float hi) {
    F2u t; t.f = make_float2(lo, hi); return t.u;
}
__device__ __forceinline__ float lo2(u64 a) { F2u t; t.u = a; return t.f.x; }
__device__ __forceinline__ float hi2(u64 a) { F2u t; t.u = a; return t.f.y; }

__device__ __forceinline__ u64 fma2(u64 a, u64 b, u64 c) {
    u64 d;
    asm("fma.rn.f32x2 %0, %1, %2, %3;" : "=l"(d) : "l"(a), "l"(b), "l"(c));
    return d;
}
__device__ __forceinline__ u64 mul2(u64 a, u64 b) {
    u64 d;
    asm("mul.rn.f32x2 %0, %1, %2;" : "=l"(d) : "l"(a), "l"(b));
    return d;
}
__device__ __forceinline__ u64 add2(u64 a, u64 b) {
    u64 d;
    asm("add.rn.f32x2 %0, %1, %2;" : "=l"(d) : "l"(a), "l"(b));
    return d;
}
__device__ __forceinline__ float ex2f(float x) {
    float y; asm("ex2.approx.f32 %0, %1;" : "=f"(y) : "f"(x)); return y;
}
__device__ __forceinline__ float rcpf(float x) {
    float y; asm("rcp.approx.f32 %0, %1;" : "=f"(y) : "f"(x)); return y;
}
__device__ __forceinline__ u64 ex2x2(u64 a) { return pack2(ex2f(lo2(a)), ex2f(hi2(a))); }
__device__ __forceinline__ u64 rcp2(u64 a)  { return pack2(rcpf(lo2(a)), rcpf(hi2(a))); }

// pre-scales: sigmoid(v) = rcp(1 + ex2(C1*v)), tanh(v) = 2*rcp(1 + ex2(C2*v)) - 1
#define C1 (-1.4426950408889634f)
#define C2 (-2.8853900817779268f)
#define SIGN2 0x8000000080000000ULL

__global__ __launch_bounds__(TPB, 16)
void gru_decoder_kernel(const float* __restrict__ hidden,
                        const float* __restrict__ w_ih,
                        const float* __restrict__ w_hh,
                        const float* __restrict__ b_ih,
                        const float* __restrict__ b_hh,
                        const float* __restrict__ w_l,
                        const float* __restrict__ b_l,
                        float* __restrict__ out,
                        int B, int step)
{
    // Extended W[i][j]: j<20 -> w_hh[i*20+j], j=20,21 -> w_ih[i*2+(j-20)]
    // WQ[p][jj][12]: p = gate pair, jj = column pair (jj=10 -> x columns):
    //   c0..3  = C1*{W[2p][j0],    W[2p][j1],    W[2p+1][j0],  W[2p+1][j1]}   (r)
    //   c4..7  = C1*{W[20+2p][j0], W[20+2p][j1], W[21+2p][j0], W[21+2p][j1]}  (z)
    //   c8..11 = C2*{W[40+2p][j0], W[40+2p][j1], W[41+2p][j0], W[41+2p][j1]}  (n)
    __shared__ __align__(16) float WQ[10][11][12];
    __shared__ __align__(16) float BQ[10][8];   // per p: {br0,br1,bz0,bz1, bhn0,bhn1,bin0,bin1}
    __shared__ __align__(16) float WLY[10][4];  // {wl0_j0, wl0_j1, wl1_j0, wl1_j1} for col pair p
    __shared__ float BL2[2];

    const int tid = threadIdx.x;

    for (int idx = tid; idx < 10 * 11 * 12; idx += TPB) {
        int p  = idx / 132;
        int r  = idx % 132;
        int jj = r / 12;
        int c  = r % 12;
        int g  = c >> 2;            // 0=r, 1=z, 2=n
        int s  = c & 3;             // bit1 = row offset, bit0 = col offset
        int row = ((g == 0) ? 2*p : (g == 1) ? 20 + 2*p : 40 + 2*p) + (s >> 1);
        int j   = ((jj < 10) ? 2*jj : 20) + (s & 1);
        float w = (j < 20) ? w_hh[row * 20 + j] : w_ih[row * 2 + (j - 20)];
        WQ[p][jj][c] = w * ((g == 2) ? C2 : C1);
    }
    if (tid < 10) {
        int p = tid;
        BQ[p][0] = C1 * (b_ih[2*p]      + b_hh[2*p]);
        BQ[p][1] = C1 * (b_ih[2*p + 1]  + b_hh[2*p + 1]);
        BQ[p][2] = C1 * (b_ih[20 + 2*p] + b_hh[20 + 2*p]);
        BQ[p][3] = C1 * (b_ih[21 + 2*p] + b_hh[21 + 2*p]);
        BQ[p][4] = C2 * b_hh[40 + 2*p];
        BQ[p][5] = C2 * b_hh[41 + 2*p];
        BQ[p][6] = C2 * b_ih[40 + 2*p];
        BQ[p][7] = C2 * b_ih[41 + 2*p];
        WLY[p][0] = w_l[2*p];
        WLY[p][1] = w_l[2*p + 1];
        WLY[p][2] = w_l[20 + 2*p];
        WLY[p][3] = w_l[21 + 2*p];
    }
    if (tid < 2) BL2[tid] = b_l[tid];
    __syncthreads();

    const int gtid = blockIdx.x * TPB + tid;
    const int role = gtid & 1;                 // even lane: pairs 0..4, odd: 5..9
    const int e0   = (gtid & ~1);              // this thread handles elements e0, e0+1
    const int own_off = 5 * role;
    const int oth_off = 5 - own_off;
    const bool valid = (e0 + 1 < B);

    // h state for both elements as natural pairs: hp[e][jj] = (h[2jj], h[2jj+1])
    u64 hp[2][10];
#pragma unroll
    for (int e2 = 0; e2 < 2; ++e2) {
        const int e = valid ? (e0 + e2) : 0;
        const float4* hsrc = (const float4*)(hidden + (size_t)e * HDIM);
#pragma unroll
        for (int q = 0; q < 5; ++q) {
            float4 v = hsrc[q];
            hp[e2][2*q]     = pack2(v.x, v.y);
            hp[e2][2*q + 1] = pack2(v.z, v.w);
        }
    }

    const u64 ONE2 = pack2(1.0f, 1.0f);
    const u64 TWO2 = pack2(2.0f, 2.0f);
    const u64 NEG1 = pack2(-1.0f, -1.0f);

    const float yb0 = role ? 0.0f : BL2[0];
    const float yb1 = role ? 0.0f : BL2[1];

    u64 xp[2] = {0, 0};                        // (x0, x1) pairs per element
    float* outb0 = out + (size_t)e0 * step * 2;
    float* outb1 = out + (size_t)(e0 + 1) * step * 2;

    const float* wqb  = &WQ[own_off][0][0];
    const float* bqb  = &BQ[own_off][0];
    const float* wlyb = &WLY[own_off][0];

#pragma unroll 1
    for (int t = 0; t < step; ++t) {
        u64 hn_new[2][5];

#pragma unroll
        for (int q = 0; q < 5; ++q) {
            const float* wq = wqb + q * 132;

            u64 Ar0[2], Ar1[2], Az0[2], Az1[2], An0[2], An1[2];
            {
                F4u R, Z, Nw;
                R.f  = *(const float4*)(wq + 0);
                Z.f  = *(const float4*)(wq + 4);
                Nw.f = *(const float4*)(wq + 8);
#pragma unroll
                for (int e2 = 0; e2 < 2; ++e2) {
                    const u64 h0 = hp[e2][0];
                    Ar0[e2] = mul2(R.u[0],  h0);
                    Ar1[e2] = mul2(R.u[1],  h0);
                    Az0[e2] = mul2(Z.u[0],  h0);
                    Az1[e2] = mul2(Z.u[1],  h0);
                    An0[e2] = mul2(Nw.u[0], h0);
                    An1[e2] = mul2(Nw.u[1], h0);
                }
            }
#pragma unroll
            for (int jj = 1; jj < 10; ++jj) {
                F4u R, Z, Nw;
                R.f  = *(const float4*)(wq + jj * 12);
                Z.f  = *(const float4*)(wq + jj * 12 + 4);
                Nw.f = *(const float4*)(wq + jj * 12 + 8);
#pragma unroll
                for (int e2 = 0; e2 < 2; ++e2) {
                    const u64 hj = hp[e2][jj];
                    Ar0[e2] = fma2(R.u[0],  hj, Ar0[e2]);
                    Ar1[e2] = fma2(R.u[1],  hj, Ar1[e2]);
                    Az0[e2] = fma2(Z.u[0],  hj, Az0[e2]);
                    Az1[e2] = fma2(Z.u[1],  hj, Az1[e2]);
                    An0[e2] = fma2(Nw.u[0], hj, An0[e2]);
                    An1[e2] = fma2(Nw.u[1], hj, An1[e2]);
                }
            }

            // x slot (jj = 10): r,z accumulate; n's x part separate (inn)
            u64 In0[2], In1[2];
            {
                F4u R, Z, Nw;
                R.f  = *(const float4*)(wq + 120);
                Z.f  = *(const float4*)(wq + 124);
                Nw.f = *(const float4*)(wq + 128);
#pragma unroll
                for (int e2 = 0; e2 < 2; ++e2) {
                    const u64 xv = xp[e2];
                    Ar0[e2] = fma2(R.u[0], xv, Ar0[e2]);
                    Ar1[e2] = fma2(R.u[1], xv, Ar1[e2]);
                    Az0[e2] = fma2(Z.u[0], xv, Az0[e2]);
                    Az1[e2] = fma2(Z.u[1], xv, Az1[e2]);
                    In0[e2] = mul2(Nw.u[0], xv);
                    In1[e2] = mul2(Nw.u[1], xv);
                }
            }

            // biases (loaded once, used for both elements)
            F4u Brz, Bn;
            Brz.f = *(const float4*)(bqb + q * 8);
            Bn.f  = *(const float4*)(bqb + q * 8 + 4);

#pragma unroll
            for (int e2 = 0; e2 < 2; ++e2) {
                const u64 rArg = add2(pack2(lo2(Ar0[e2]) + hi2(Ar0[e2]),
                                            lo2(Ar1[e2]) + hi2(Ar1[e2])), Brz.u[0]);
                const u64 zArg = add2(pack2(lo2(Az0[e2]) + hi2(Az0[e2]),
                                            lo2(Az1[e2]) + hi2(Az1[e2])), Brz.u[1]);
                const u64 hnv  = add2(pack2(lo2(An0[e2]) + hi2(An0[e2]),
                                            lo2(An1[e2]) + hi2(An1[e2])), Bn.u[0]);
                const u64 innv = add2(pack2(lo2(In0[e2]) + hi2(In0[e2]),
                                            lo2(In1[e2]) + hi2(In1[e2])), Bn.u[1]);

                const u64 rv = rcp2(add2(ex2x2(rArg), ONE2));
                const u64 zv = rcp2(add2(ex2x2(zArg), ONE2));
                const u64 s  = fma2(rv, hnv, innv);
                const u64 nv = fma2(TWO2, rcp2(add2(ex2x2(s), ONE2)), NEG1);

                const u64 hold = hp[e2][own_off + q];
                const u64 t1 = fma2(zv, hold, nv);            // z*h + n
                hn_new[e2][q] = fma2(zv ^ SIGN2, nv, t1);     // (z*h+n) - z*n
            }
        }

        // partial y over own 10 dims for both elements
        u64 Y0[2], Y1[2];
        {
            F4u wl; wl.f = *(const float4*)(wlyb);
#pragma unroll
            for (int e2 = 0; e2 < 2; ++e2) {
                Y0[e2] = mul2(wl.u[0], hn_new[e2][0]);
                Y1[e2] = mul2(wl.u[1], hn_new[e2][0]);
            }
#pragma unroll
            for (int q = 1; q < 5; ++q) {
                wl.f = *(const float4*)(wlyb + q * 4);
#pragma unroll
                for (int e2 = 0; e2 < 2; ++e2) {
                    Y0[e2] = fma2(wl.u[0], hn_new[e2][q], Y0[e2]);
                    Y1[e2] = fma2(wl.u[1], hn_new[e2][q], Y1[e2]);
                }
            }
        }

        u64 yfull[2];
#pragma unroll
        for (int e2 = 0; e2 < 2; ++e2) {
            const float y0p = lo2(Y0[e2]) + hi2(Y0[e2]) + yb0;
            const float y1p = lo2(Y1[e2]) + hi2(Y1[e2]) + yb1;
            u64 ym = pack2(y0p, y1p);
            u64 yo = __shfl_xor_sync(0xFFFFFFFFu, ym, 1);
            yfull[e2] = add2(ym, yo);          // both lanes now hold full y
        }

        // exchange h halves with partner lane, update state
#pragma unroll
        for (int q = 0; q < 5; ++q) {
#pragma unroll
            for (int e2 = 0; e2 < 2; ++e2) {
                const u64 pq = __shfl_xor_sync(0xFFFFFFFFu, hn_new[e2][q], 1);
                hp[e2][own_off + q] = hn_new[e2][q];
                hp[e2][oth_off + q] = pq;
            }
        }

        // output time-reversed: y_t -> slot (step-1-t); even lane stores both
        if (!role && valid) {
            F2u ya; ya.u = yfull[0];
            F2u yb; yb.u = yfull[1];
            const size_t off = (size_t)(step - 1 - t) * 2;
            *(float2*)(outb0 + off) = ya.f;
            *(float2*)(outb1 + off) = yb.f;
        }
        xp[0] = yfull[0];
        xp[1] = yfull[1];
    }
}

extern "C" void kernel_launch(void* const* d_in, const int* in_sizes, int n_in,
                              void* d_out, int out_size) {
    const float* hidden = (const float*)d_in[0];
    const float* w_ih   = (const float*)d_in[1];
    const float* w_hh   = (const float*)d_in[2];
    const float* b_ih   = (const float*)d_in[3];
    const float* b_hh   = (const float*)d_in[4];
    const float* w_l    = (const float*)d_in[5];
    const float* b_l    = (const float*)d_in[6];

    const int B = in_sizes[0] / HDIM;        // hidden is (1, B, 20)
    const int step = out_size / (2 * B);     // out is (B, step, 2)

    // threads = B total (2 threads per element-pair, 2 elements per thread)
    const int nthreads = B;
    const int grid = (nthreads + TPB - 1) / TPB;
    gru_decoder_kernel<<<grid, TPB>>>(hidden, w_ih, w_hh, b_ih, b_hh, w_l, b_l,
                                      (float*)d_out, B, step);
}

// round 7
// speedup vs baseline: 1.6168x; 1.6168x over previous
#include <cuda_runtime.h>
#include <cuda_bf16.h>
#include <cstdint>

#define HDIM 20
#define TPB 32   // one warp per block; lane parity = role; 2 elements per thread

typedef unsigned long long u64;

union F2u { float2 f; u64 u; };
union F4u { float4 f; u64 u[2]; };

__device__ __forceinline__ u64 pack2(float lo, float hi) {
    F2u t; t.f = make_float2(lo, hi); return t.u;
}
__device__ __forceinline__ float lo2(u64 a) { F2u t; t.u = a; return t.f.x; }
__device__ __forceinline__ float hi2(u64 a) { F2u t; t.u = a; return t.f.y; }

__device__ __forceinline__ u64 fma2(u64 a, u64 b, u64 c) {
    u64 d;
    asm("fma.rn.f32x2 %0, %1, %2, %3;" : "=l"(d) : "l"(a), "l"(b), "l"(c));
    return d;
}
__device__ __forceinline__ u64 mul2(u64 a, u64 b) {
    u64 d;
    asm("mul.rn.f32x2 %0, %1, %2;" : "=l"(d) : "l"(a), "l"(b));
    return d;
}
__device__ __forceinline__ u64 add2(u64 a, u64 b) {
    u64 d;
    asm("add.rn.f32x2 %0, %1, %2;" : "=l"(d) : "l"(a), "l"(b));
    return d;
}
__device__ __forceinline__ float ex2f(float x) {
    float y; asm("ex2.approx.f32 %0, %1;" : "=f"(y) : "f"(x)); return y;
}
__device__ __forceinline__ float rcpf(float x) {
    float y; asm("rcp.approx.f32 %0, %1;" : "=f"(y) : "f"(x)); return y;
}
__device__ __forceinline__ u64 ex2x2(u64 a) { return pack2(ex2f(lo2(a)), ex2f(hi2(a))); }
__device__ __forceinline__ u64 rcp2(u64 a)  { return pack2(rcpf(lo2(a)), rcpf(hi2(a))); }

// pre-scales: sigmoid(v) = rcp(1 + ex2(C1*v)), tanh(v) = 2*rcp(1 + ex2(C2*v)) - 1
#define C1 (-1.4426950408889634f)
#define C2 (-2.8853900817779268f)
#define SIGN2 0x8000000080000000ULL

__global__ __launch_bounds__(TPB, 2)   // allow up to 255 regs; occupancy is grid-limited anyway
void gru_decoder_kernel(const float* __restrict__ hidden,
                        const float* __restrict__ w_ih,
                        const float* __restrict__ w_hh,
                        const float* __restrict__ b_ih,
                        const float* __restrict__ b_hh,
                        const float* __restrict__ w_l,
                        const float* __restrict__ b_l,
                        float* __restrict__ out,
                        int B, int step)
{
    // Extended W[i][j]: j<20 -> w_hh[i*20+j], j=20,21 -> w_ih[i*2+(j-20)]
    // WQ[p][jj][12]: p = gate pair, jj = column pair (jj=10 -> x columns):
    //   c0..3  = C1*{W[2p][j0],    W[2p][j1],    W[2p+1][j0],  W[2p+1][j1]}   (r)
    //   c4..7  = C1*{W[20+2p][j0], W[20+2p][j1], W[21+2p][j0], W[21+2p][j1]}  (z)
    //   c8..11 = C2*{W[40+2p][j0], W[40+2p][j1], W[41+2p][j0], W[41+2p][j1]}  (n)
    __shared__ __align__(16) float WQ[10][11][12];
    __shared__ __align__(16) float BQ[10][8];   // per p: {br0,br1,bz0,bz1, bhn0,bhn1,bin0,bin1}
    __shared__ __align__(16) float WLY[10][4];  // {wl0_j0, wl0_j1, wl1_j0, wl1_j1} for col pair p
    __shared__ float BL2[2];

    const int tid = threadIdx.x;

    for (int idx = tid; idx < 10 * 11 * 12; idx += TPB) {
        int p  = idx / 132;
        int r  = idx % 132;
        int jj = r / 12;
        int c  = r % 12;
        int g  = c >> 2;            // 0=r, 1=z, 2=n
        int s  = c & 3;             // bit1 = row offset, bit0 = col offset
        int row = ((g == 0) ? 2*p : (g == 1) ? 20 + 2*p : 40 + 2*p) + (s >> 1);
        int j   = ((jj < 10) ? 2*jj : 20) + (s & 1);
        float w = (j < 20) ? w_hh[row * 20 + j] : w_ih[row * 2 + (j - 20)];
        WQ[p][jj][c] = w * ((g == 2) ? C2 : C1);
    }
    if (tid < 10) {
        int p = tid;
        BQ[p][0] = C1 * (b_ih[2*p]      + b_hh[2*p]);
        BQ[p][1] = C1 * (b_ih[2*p + 1]  + b_hh[2*p + 1]);
        BQ[p][2] = C1 * (b_ih[20 + 2*p] + b_hh[20 + 2*p]);
        BQ[p][3] = C1 * (b_ih[21 + 2*p] + b_hh[21 + 2*p]);
        BQ[p][4] = C2 * b_hh[40 + 2*p];
        BQ[p][5] = C2 * b_hh[41 + 2*p];
        BQ[p][6] = C2 * b_ih[40 + 2*p];
        BQ[p][7] = C2 * b_ih[41 + 2*p];
        WLY[p][0] = w_l[2*p];
        WLY[p][1] = w_l[2*p + 1];
        WLY[p][2] = w_l[20 + 2*p];
        WLY[p][3] = w_l[21 + 2*p];
    }
    if (tid < 2) BL2[tid] = b_l[tid];
    __syncthreads();

    const int gtid = blockIdx.x * TPB + tid;
    const int role = gtid & 1;                 // even lane: pairs 0..4, odd: 5..9
    const int e0   = (gtid & ~1);              // this thread handles elements e0, e0+1
    const int own_off = 5 * role;
    const int oth_off = 5 - own_off;
    const bool valid = (e0 + 1 < B);

    // h state for both elements as natural pairs: hp[e][jj] = (h[2jj], h[2jj+1])
    u64 hp[2][10];
#pragma unroll
    for (int e2 = 0; e2 < 2; ++e2) {
        const int e = valid ? (e0 + e2) : 0;
        const float4* hsrc = (const float4*)(hidden + (size_t)e * HDIM);
#pragma unroll
        for (int q = 0; q < 5; ++q) {
            float4 v = hsrc[q];
            hp[e2][2*q]     = pack2(v.x, v.y);
            hp[e2][2*q + 1] = pack2(v.z, v.w);
        }
    }

    const u64 ONE2 = pack2(1.0f, 1.0f);
    const u64 TWO2 = pack2(2.0f, 2.0f);
    const u64 NEG1 = pack2(-1.0f, -1.0f);

    const float yb0 = role ? 0.0f : BL2[0];
    const float yb1 = role ? 0.0f : BL2[1];

    const float* wqb  = &WQ[own_off][0][0];

    // ---- hoist loop-invariant smem into registers (loaded once, live 200 steps) ----
    F4u BrzC[5], BnC[5];            // biases: 40 regs
    F4u XRc[5], XZc[5], XNc[5];     // x-slot weights: 60 regs
    F4u WLc[5];                     // y weights: 20 regs
#pragma unroll
    for (int q = 0; q < 5; ++q) {
        BrzC[q].f = *(const float4*)(&BQ[own_off + q][0]);
        BnC[q].f  = *(const float4*)(&BQ[own_off + q][4]);
        XRc[q].f  = *(const float4*)(wqb + q * 132 + 120);
        XZc[q].f  = *(const float4*)(wqb + q * 132 + 124);
        XNc[q].f  = *(const float4*)(wqb + q * 132 + 128);
        WLc[q].f  = *(const float4*)(&WLY[own_off + q][0]);
    }

    u64 xp[2] = {0, 0};                        // (x0, x1) pairs per element
    float* outb0 = out + (size_t)e0 * step * 2;
    float* outb1 = out + (size_t)(e0 + 1) * step * 2;

#pragma unroll 1
    for (int t = 0; t < step; ++t) {
        u64 hn_new[2][5];

#pragma unroll
        for (int q = 0; q < 5; ++q) {
            const float* wq = wqb + q * 132;

            u64 Ar0[2], Ar1[2], Az0[2], Az1[2], An0[2], An1[2];
            {
                F4u R, Z, Nw;
                R.f  = *(const float4*)(wq + 0);
                Z.f  = *(const float4*)(wq + 4);
                Nw.f = *(const float4*)(wq + 8);
#pragma unroll
                for (int e2 = 0; e2 < 2; ++e2) {
                    const u64 h0 = hp[e2][0];
                    Ar0[e2] = mul2(R.u[0],  h0);
                    Ar1[e2] = mul2(R.u[1],  h0);
                    Az0[e2] = mul2(Z.u[0],  h0);
                    Az1[e2] = mul2(Z.u[1],  h0);
                    An0[e2] = mul2(Nw.u[0], h0);
                    An1[e2] = mul2(Nw.u[1], h0);
                }
            }
#pragma unroll
            for (int jj = 1; jj < 10; ++jj) {
                F4u R, Z, Nw;
                R.f  = *(const float4*)(wq + jj * 12);
                Z.f  = *(const float4*)(wq + jj * 12 + 4);
                Nw.f = *(const float4*)(wq + jj * 12 + 8);
#pragma unroll
                for (int e2 = 0; e2 < 2; ++e2) {
                    const u64 hj = hp[e2][jj];
                    Ar0[e2] = fma2(R.u[0],  hj, Ar0[e2]);
                    Ar1[e2] = fma2(R.u[1],  hj, Ar1[e2]);
                    Az0[e2] = fma2(Z.u[0],  hj, Az0[e2]);
                    Az1[e2] = fma2(Z.u[1],  hj, Az1[e2]);
                    An0[e2] = fma2(Nw.u[0], hj, An0[e2]);
                    An1[e2] = fma2(Nw.u[1], hj, An1[e2]);
                }
            }

            // x slot (jj = 10) from REGISTER-cached weights; n's x part separate (inn)
            u64 In0[2], In1[2];
#pragma unroll
            for (int e2 = 0; e2 < 2; ++e2) {
                const u64 xv = xp[e2];
                Ar0[e2] = fma2(XRc[q].u[0], xv, Ar0[e2]);
                Ar1[e2] = fma2(XRc[q].u[1], xv, Ar1[e2]);
                Az0[e2] = fma2(XZc[q].u[0], xv, Az0[e2]);
                Az1[e2] = fma2(XZc[q].u[1], xv, Az1[e2]);
                In0[e2] = mul2(XNc[q].u[0], xv);
                In1[e2] = mul2(XNc[q].u[1], xv);
            }

#pragma unroll
            for (int e2 = 0; e2 < 2; ++e2) {
                const u64 rArg = add2(pack2(lo2(Ar0[e2]) + hi2(Ar0[e2]),
                                            lo2(Ar1[e2]) + hi2(Ar1[e2])), BrzC[q].u[0]);
                const u64 zArg = add2(pack2(lo2(Az0[e2]) + hi2(Az0[e2]),
                                            lo2(Az1[e2]) + hi2(Az1[e2])), BrzC[q].u[1]);
                const u64 hnv  = add2(pack2(lo2(An0[e2]) + hi2(An0[e2]),
                                            lo2(An1[e2]) + hi2(An1[e2])), BnC[q].u[0]);
                const u64 innv = add2(pack2(lo2(In0[e2]) + hi2(In0[e2]),
                                            lo2(In1[e2]) + hi2(In1[e2])), BnC[q].u[1]);

                const u64 rv = rcp2(add2(ex2x2(rArg), ONE2));
                const u64 zv = rcp2(add2(ex2x2(zArg), ONE2));
                const u64 s  = fma2(rv, hnv, innv);
                const u64 nv = fma2(TWO2, rcp2(add2(ex2x2(s), ONE2)), NEG1);

                const u64 hold = hp[e2][own_off + q];
                const u64 t1 = fma2(zv, hold, nv);            // z*h + n
                hn_new[e2][q] = fma2(zv ^ SIGN2, nv, t1);     // (z*h+n) - z*n
            }
        }

        // partial y over own 10 dims for both elements (register-cached weights)
        u64 Y0[2], Y1[2];
#pragma unroll
        for (int e2 = 0; e2 < 2; ++e2) {
            Y0[e2] = mul2(WLc[0].u[0], hn_new[e2][0]);
            Y1[e2] = mul2(WLc[0].u[1], hn_new[e2][0]);
        }
#pragma unroll
        for (int q = 1; q < 5; ++q) {
#pragma unroll
            for (int e2 = 0; e2 < 2; ++e2) {
                Y0[e2] = fma2(WLc[q].u[0], hn_new[e2][q], Y0[e2]);
                Y1[e2] = fma2(WLc[q].u[1], hn_new[e2][q], Y1[e2]);
            }
        }

        u64 yfull[2];
#pragma unroll
        for (int e2 = 0; e2 < 2; ++e2) {
            const float y0p = lo2(Y0[e2]) + hi2(Y0[e2]) + yb0;
            const float y1p = lo2(Y1[e2]) + hi2(Y1[e2]) + yb1;
            u64 ym = pack2(y0p, y1p);
            u64 yo = __shfl_xor_sync(0xFFFFFFFFu, ym, 1);
            yfull[e2] = add2(ym, yo);          // both lanes now hold full y
        }

        // exchange h halves with partner lane, update state
#pragma unroll
        for (int q = 0; q < 5; ++q) {
#pragma unroll
            for (int e2 = 0; e2 < 2; ++e2) {
                const u64 pq = __shfl_xor_sync(0xFFFFFFFFu, hn_new[e2][q], 1);
                hp[e2][own_off + q] = hn_new[e2][q];
                hp[e2][oth_off + q] = pq;
            }
        }

        // output time-reversed: y_t -> slot (step-1-t); even lane stores both
        if (!role && valid) {
            F2u ya; ya.u = yfull[0];
            F2u yb; yb.u = yfull[1];
            const size_t off = (size_t)(step - 1 - t) * 2;
            *(float2*)(outb0 + off) = ya.f;
            *(float2*)(outb1 + off) = yb.f;
        }
        xp[0] = yfull[0];
        xp[1] = yfull[1];
    }
}

extern "C" void kernel_launch(void* const* d_in, const int* in_sizes, int n_in,
                              void* d_out, int out_size) {
    const float* hidden = (const float*)d_in[0];
    const float* w_ih   = (const float*)d_in[1];
    const float* w_hh   = (const float*)d_in[2];
    const float* b_ih   = (const float*)d_in[3];
    const float* b_hh   = (const float*)d_in[4];
    const float* w_l    = (const float*)d_in[5];
    const float* b_l    = (const float*)d_in[6];

    const int B = in_sizes[0] / HDIM;        // hidden is (1, B, 20)
    const int step = out_size / (2 * B);     // out is (B, step, 2)

    // threads = B total (2 threads per element-pair, 2 elements per thread)
    const int nthreads = B;
    const int grid = (nthreads + TPB - 1) / TPB;
    gru_decoder_kernel<<<grid, TPB>>>(hidden, w_ih, w_hh, b_ih, b_hh, w_l, b_l,
                                      (float*)d_out, B, step);
}